// round 15
// baseline (speedup 1.0000x reference)
#include <cuda_runtime.h>
#include <math.h>

#define NB 8
#define NT 128
#define NU 64
#define NU1 65
#define NV 512
#define NEGF (-1e30f)

// joint tiling: 8 t-rows x 16 u-cols per CTA, 128 threads
#define TTILE 8
#define UTILE 16
#define UT 5                        // u tiles covering 65
#define TT (NT / TTILE)             // 16 t tiles
#define TILES_PER_B (UT * TT)       // 80
#define JOINT_CTAS (NB * TILES_PER_B)  // 1280
#define TK 32

// dp staging: 32-row t-chunks (4 chunks), padded stride 66
#define CH 32
#define SST 66
#define NCHUNK 4
#define TILES_PER_Q 20              // tiles per (batch, 32-row quarter)

// shared pool (union; branches CTA-exclusive)
//   dp:    sLPB[CH*SST] | sLPL[CH*SST] | bnd[2][4] | sFin  -> 4233 floats
//   joint: As[8*36]=288 | Bs[16*36]=576                     -> 864 floats
#define POOL_FLOATS (2 * CH * SST + 16)   // 4240 floats = 16960 B

// ---------------- device scratch (no allocations allowed) ----------------
__device__ __align__(16) float g_lpb[NB * NT * NU1];  // log P(blank)  (b,t,u)
__device__ __align__(16) float g_lpl[NB * NT * NU];   // log P(label)  (b,t,u)
__device__ float g_cost[NB];
__device__ unsigned int g_rdy[NB * NCHUNK];  // tiles done per (b, quarter)
__device__ unsigned int g_done;              // dp CTAs done (self-reset)

__device__ __forceinline__ float lae(float a, float c) {
    float mx = fmaxf(a, c);
    float mn = fminf(a, c);
    return mx + __logf(1.0f + __expf(mn - mx));
}

__global__ void __launch_bounds__(128)
rnnt_fused_kernel(const float* __restrict__ trans,
                  const float* __restrict__ pred,
                  const int* __restrict__ labels,
                  const int* __restrict__ act_lens,
                  const int* __restrict__ label_lens,
                  float* __restrict__ out) {
    __shared__ __align__(16) float pool[POOL_FLOATS];
    int tid = threadIdx.x;

    if (blockIdx.x < JOINT_CTAS) {
        // ==== JOINT: exp-GEMM (R12 inner loop), 8x16 tile, 128 threads ====
        float* As = pool;                // [8][36]
        float* Bs = pool + TTILE * 36;   // [16][36]

        int blk = blockIdx.x;
        int b   = blk / TILES_PER_B;
        int rem = blk - b * TILES_PER_B;
        int t0  = (rem / UT) * TTILE;
        int u0  = (rem % UT) * UTILE;

        const float* Tb = trans + ((size_t)(b * NT + t0)) * NV;
        const float* Pb = pred + ((size_t)b * NU1) * NV;

        int tx = tid & 15;   // u in tile
        int ty = tid >> 4;   // t in tile (0..7)
        float acc = 0.f;
        for (int k0 = 0; k0 < NV; k0 += TK) {
            // stage A: 8x32 = 256 entries, 2/thread
#pragma unroll
            for (int i = 0; i < 2; i++) {
                int idx = tid + i * 128;
                int rr = idx >> 5;
                int cc = idx & 31;
                As[rr * 36 + cc] = __expf(Tb[(size_t)rr * NV + k0 + cc]);
            }
            // stage B: 16x32 = 512 entries, 4/thread
#pragma unroll
            for (int i = 0; i < 4; i++) {
                int idx = tid + i * 128;
                int rr = idx >> 5;
                int cc = idx & 31;
                int uu = u0 + rr;
                Bs[rr * 36 + cc] = (uu < NU1)
                    ? __expf(Pb[(size_t)uu * NV + k0 + cc]) : 0.f;
            }
            __syncthreads();
            const float4* a4 = (const float4*)(As + ty * 36);
            const float4* b4 = (const float4*)(Bs + tx * 36);
#pragma unroll
            for (int k = 0; k < TK / 4; k++) {
                float4 av = a4[k];
                float4 bv = b4[k];
                acc += av.x * bv.x + av.y * bv.y + av.z * bv.z + av.w * bv.w;
            }
            __syncthreads();
        }

        // epilogue: lse + gather blank/label logits
        int t = t0 + ty;
        int u = u0 + tx;
        if (u < NU1) {
            float lse = logf(acc);
            const float* trow = Tb + (size_t)ty * NV;
            const float* prow = Pb + (size_t)u * NV;
            g_lpb[(b * NT + t) * NU1 + u] = trow[0] + prow[0] - lse;
            if (u < NU) {
                int lab = labels[b * NU + u];
                g_lpl[(b * NT + t) * NU + u] = trow[lab] + prow[lab] - lse;
            }
        }
        __syncthreads();
        if (tid == 0) {
            __threadfence();                       // release lpb/lpl
            atomicAdd(&g_rdy[b * NCHUNK + (t0 >> 5)], 1u);
        }
    } else {
        // ====== DP: 4-warp barrier wavefront (R12 logic), 32-row chunks ===
        float* sLPB = pool;                     // CH*SST
        float* sLPL = pool + CH * SST;          // CH*SST
        float* bnd  = pool + 2 * CH * SST;      // [2][4]
        float* sFin = pool + 2 * CH * SST + 8;  // 1

        int b = blockIdx.x - JOINT_CTAS;
        int lane = tid & 31;
        int w    = tid >> 5;
        int u    = tid;          // active u < NU1 (warps 0-2)

        int te = act_lens[b] - 1;
        int ue = label_lens[b];

        float a = 0.f;   // rolling alpha register for this thread's u

        for (int chunk = 0; chunk < NCHUNK; chunk++) {
            // wait for this quarter's 20 tiles (chunk>0 also needs lpb row
            // t0c-1, covered by the previous quarter's wait). Single wave.
            if (tid == 0) {
                volatile unsigned int* p = &g_rdy[b * NCHUNK + chunk];
                while (*p < (unsigned)TILES_PER_Q) __nanosleep(64);
                __threadfence();               // acquire lpb/lpl
            }
            __syncthreads();

            int t0c    = chunk * CH;
            int base_b = (chunk == 0) ? 0 : (t0c - 1);
            int base_l = t0c;

            // stage tables (L2-coherent loads; writers are other SMs)
            {
                const float* gB = g_lpb + ((size_t)(b * NT + base_b)) * NU1;
                for (int i = tid; i < CH * NU1; i += 128) {
                    int r = i / NU1, c = i - r * NU1;
                    sLPB[r * SST + c] = __ldcg(gB + i);
                }
                const float* gL = g_lpl + ((size_t)(b * NT + base_l)) * NU;
                for (int i = tid; i < CH * NU; i += 128) {
                    sLPL[(i >> 6) * SST + (i & 63)] = __ldcg(gL + i);
                }
            }
            __syncthreads();

            int dl_lo = (chunk == 0) ? 1 : 0;   // (0,0) seeded a=0
            for (int dl = dl_lo; dl <= CH - 1 + NU1 - 1; dl++) {
                int p = dl & 1;
                float up = __shfl_up_sync(0xffffffffu, a, 1);
                if (lane == 0 && w > 0) up = bnd[(p ^ 1) * 4 + (w - 1)];

                int t = t0c + dl - u;
                if (u < NU1 && t >= t0c && t <= t0c + CH - 1) {
                    float pa = (t >= 1)
                        ? a + sLPB[(t - 1 - base_b) * SST + u] : NEGF;
                    float pb = (u >= 1)
                        ? up + sLPL[(t - base_l) * SST + (u - 1)] : NEGF;
                    a = lae(pa, pb);
                    if (t == te && u == ue) *sFin = a;
                }
                if (lane == 31) bnd[p * 4 + w] = a;
                __syncthreads();
            }
        }

        if (tid == 0) {
            float lpb_fin = __ldcg(&g_lpb[(size_t)(b * NT + te) * NU1 + ue]);
            g_cost[b] = -(*sFin + lpb_fin);
            __threadfence();
            unsigned int prev = atomicAdd(&g_done, 1u);
            if (prev == NB - 1) {   // last dp CTA: fixed-order deterministic sum
                float s = 0.f;
                volatile float* vc = g_cost;
                for (int i = 0; i < NB; i++) s += vc[i];
                out[0] = s;
                g_done = 0;          // self-reset for next replay
            }
#pragma unroll
            for (int q = 0; q < NCHUNK; q++)    // self-reset (all observed)
                g_rdy[b * NCHUNK + q] = 0;
        }
    }
}

extern "C" void kernel_launch(void* const* d_in, const int* in_sizes, int n_in,
                              void* d_out, int out_size) {
    const float* trans   = (const float*)d_in[0];  // (B,T,V)
    const float* pred    = (const float*)d_in[1];  // (B,U1,V)
    const int*   labels  = (const int*)d_in[2];    // (B,U)
    const int*   act_l   = (const int*)d_in[3];    // (B,)
    const int*   label_l = (const int*)d_in[4];    // (B,)
    float*       out     = (float*)d_out;

    rnnt_fused_kernel<<<JOINT_CTAS + NB, 128>>>(trans, pred, labels,
                                                act_l, label_l, out);
}

// round 16
// speedup vs baseline: 1.2538x; 1.2538x over previous
#include <cuda_runtime.h>
#include <math.h>

#define NB 8
#define NT 128
#define NU 64
#define NU1 65
#define NV 512
#define NEGF (-1e30f)

#define UT 5                      // u tiles (16 wide) covering 65
#define TT 8                      // t tiles
#define TILES_PER_B (UT * TT)     // 40
#define JOINT_CTAS (NB * TILES_PER_B)  // 320
#define TK 32
#define KH 256                    // k-half size (2 groups)
#define NKI (KH / TK)             // 8 iterations per group

// dp staging: 64-row t-chunks, padded stride 66 (conflict-free diagonals)
#define CH 64
#define SST 66

// shared pool (union; branches CTA-exclusive)
//   dp:    sLPB[CH*SST] | sLPL[CH*SST] | bnd[2][16] | sFin   -> 8481 floats
//   joint: As0,Bs0,As1,Bs1 (4 x 16*36 = 2304) | red[256]     -> 2560 floats
#define POOL_FLOATS (2 * CH * SST + 36)   // 8484 floats = 33936 B

// ---------------- device scratch (no allocations allowed) ----------------
__device__ __align__(16) float g_lpb[NB * NT * NU1];  // log P(blank)  (b,t,u)
__device__ __align__(16) float g_lpl[NB * NT * NU];   // log P(label)  (b,t,u)
__device__ float g_cost[NB];
__device__ unsigned int g_rdy[NB * 2];   // [b][half-of-T]: tiles done
__device__ unsigned int g_done;          // dp CTAs done (self-reset)

__device__ __forceinline__ float lae(float a, float c) {
    float mx = fmaxf(a, c);
    float mn = fminf(a, c);
    return mx + __logf(1.0f + __expf(mn - mx));
}

__global__ void __launch_bounds__(512)
rnnt_fused_kernel(const float* __restrict__ trans,
                  const float* __restrict__ pred,
                  const int* __restrict__ labels,
                  const int* __restrict__ act_lens,
                  const int* __restrict__ label_lens,
                  float* __restrict__ out) {
    __shared__ __align__(16) float pool[POOL_FLOATS];
    int tid = threadIdx.x;

    if (blockIdx.x < JOINT_CTAS) {
        // ==== JOINT: R12 exp-GEMM, split-k over 2 thread groups ===========
        int h  = tid >> 8;        // k-half (0: k<256, 1: k>=256)
        int lt = tid & 255;       // local tid within group
        float* As  = pool + h * 2 * 16 * 36;   // group-private tiles
        float* Bs  = As + 16 * 36;
        float* red = pool + 4 * 16 * 36;       // 256-float partial buffer

        int blk = blockIdx.x;
        int b   = blk / TILES_PER_B;
        int rem = blk - b * TILES_PER_B;
        int t0  = (rem / UT) * 16;
        int u0  = (rem % UT) * 16;

        const float* Tb = trans + ((size_t)(b * NT + t0)) * NV + h * KH;
        const float* Pb = pred + ((size_t)b * NU1) * NV + h * KH;

        int tx = lt & 15;   // u in tile
        int ty = lt >> 4;   // t in tile
        float acc = 0.f;
        for (int k0 = 0; k0 < KH; k0 += TK) {
#pragma unroll
            for (int i = 0; i < 2; i++) {
                int idx = lt + i * 256;
                int rr = idx >> 5;
                int cc = idx & 31;
                As[rr * 36 + cc] = __expf(Tb[(size_t)rr * NV + k0 + cc]);
                int uu = u0 + rr;
                Bs[rr * 36 + cc] = (uu < NU1)
                    ? __expf(Pb[(size_t)uu * NV + k0 + cc]) : 0.f;
            }
            __syncthreads();
            const float4* a4 = (const float4*)(As + ty * 36);
            const float4* b4 = (const float4*)(Bs + tx * 36);
#pragma unroll
            for (int k = 0; k < TK / 4; k++) {
                float4 av = a4[k];
                float4 bv = b4[k];
                acc += av.x * bv.x + av.y * bv.y + av.z * bv.z + av.w * bv.w;
            }
            __syncthreads();
        }

        // combine k-halves: h=1 publishes its partial, h=0 finishes
        if (h == 1) red[lt] = acc;
        __syncthreads();

        if (h == 0) {
            acc += red[lt];
            int t = t0 + ty;
            int u = u0 + tx;
            if (u < NU1) {
                float lse = logf(acc);
                const float* trow = trans + ((size_t)(b * NT + t)) * NV;
                const float* prow = pred + ((size_t)(b * NU1 + u)) * NV;
                g_lpb[(b * NT + t) * NU1 + u] = trow[0] + prow[0] - lse;
                if (u < NU) {
                    int lab = labels[b * NU + u];
                    g_lpl[(b * NT + t) * NU + u] = trow[lab] + prow[lab] - lse;
                }
            }
        }
        __syncthreads();
        if (tid == 0) {
            __threadfence();                       // release lpb/lpl
            atomicAdd(&g_rdy[b * 2 + (t0 >= 64)], 1u);
        }
    } else {
        // ========== DP: 8-warp barrier wavefront (R12), per-half waits ====
        float* sLPB = pool;                     // CH*SST
        float* sLPL = pool + CH * SST;          // CH*SST
        float* bnd  = pool + 2 * CH * SST;      // [2][16]
        float* sFin = pool + 2 * CH * SST + 32; // 1

        int b = blockIdx.x - JOINT_CTAS;
        int lane = tid & 31;
        int w    = tid >> 5;
        int u    = tid;          // active u < NU1 (warps 0-2)

        int te = act_lens[b] - 1;
        int ue = label_lens[b];

        float a = 0.f;   // rolling alpha register for this thread's u

        for (int chunk = 0; chunk < 2; chunk++) {
            // wait for this half's 20 tiles (chunk 1 also needs lpb row 63,
            // covered by chunk 0's wait). Grid is single-wave resident.
            if (tid == 0) {
                volatile unsigned int* p = &g_rdy[b * 2 + chunk];
                while (*p < 20u) __nanosleep(64);
                __threadfence();               // acquire lpb/lpl
            }
            __syncthreads();

            int t0c    = chunk * CH;
            int base_b = (chunk == 0) ? 0 : (t0c - 1);
            int base_l = t0c;

            // stage tables (L2-coherent loads; writers are other SMs)
            {
                const float* gB = g_lpb + ((size_t)(b * NT + base_b)) * NU1;
                for (int i = tid; i < CH * NU1; i += 512) {
                    int r = i / NU1, c = i - r * NU1;
                    sLPB[r * SST + c] = __ldcg(gB + i);
                }
                const float* gL = g_lpl + ((size_t)(b * NT + base_l)) * NU;
                for (int i = tid; i < CH * NU; i += 512) {
                    sLPL[(i >> 6) * SST + (i & 63)] = __ldcg(gL + i);
                }
            }
            __syncthreads();

            int dl_lo = (chunk == 0) ? 1 : 0;   // (0,0) seeded a=0
            for (int dl = dl_lo; dl <= CH - 1 + NU1 - 1; dl++) {
                int p = dl & 1;
                float up = __shfl_up_sync(0xffffffffu, a, 1);
                if (lane == 0 && w > 0) up = bnd[(p ^ 1) * 16 + (w - 1)];

                int t = t0c + dl - u;
                if (u < NU1 && t >= t0c && t <= t0c + CH - 1) {
                    float pa = (t >= 1)
                        ? a + sLPB[(t - 1 - base_b) * SST + u] : NEGF;
                    float pb = (u >= 1)
                        ? up + sLPL[(t - base_l) * SST + (u - 1)] : NEGF;
                    a = lae(pa, pb);
                    if (t == te && u == ue) *sFin = a;
                }
                if (lane == 31) bnd[p * 16 + w] = a;
                __syncthreads();
            }
        }

        if (tid == 0) {
            float lpb_fin = __ldcg(&g_lpb[(size_t)(b * NT + te) * NU1 + ue]);
            g_cost[b] = -(*sFin + lpb_fin);
            __threadfence();
            unsigned int prev = atomicAdd(&g_done, 1u);
            if (prev == NB - 1) {   // last dp CTA: fixed-order deterministic sum
                float s = 0.f;
                volatile float* vc = g_cost;
                for (int i = 0; i < NB; i++) s += vc[i];
                out[0] = s;
                g_done = 0;          // self-reset for next replay
            }
            g_rdy[b * 2] = 0;        // self-reset (all arrivals observed)
            g_rdy[b * 2 + 1] = 0;
        }
    }
}

extern "C" void kernel_launch(void* const* d_in, const int* in_sizes, int n_in,
                              void* d_out, int out_size) {
    const float* trans   = (const float*)d_in[0];  // (B,T,V)
    const float* pred    = (const float*)d_in[1];  // (B,U1,V)
    const int*   labels  = (const int*)d_in[2];    // (B,U)
    const int*   act_l   = (const int*)d_in[3];    // (B,)
    const int*   label_l = (const int*)d_in[4];    // (B,)
    float*       out     = (float*)d_out;

    rnnt_fused_kernel<<<JOINT_CTAS + NB, 512>>>(trans, pred, labels,
                                                act_l, label_l, out);
}